// round 13
// baseline (speedup 1.0000x reference)
#include <cuda_runtime.h>
#include <cuda_fp16.h>
#include <cstdint>

// out[n,o] = sum_i x[n,i] * sign(W[o,i]) + b[o],  N=IN=OUT=4096, fp32 in/out.
//
// Legacy HMMA f32-acc mma.sync (tcgen05 not emittable at compute_103).
// Round-11: barrier-crossing MMA carry -> tensor 82.2%. Remaining idle is wave
// quantization (1024 tiles / 296 slots = 3.46 waves -> 86.5% ceiling).
// Round-12/13: 1D grid, first 888 CTAs = full 128x128 tiles (3 exact waves),
// last 136 tiles split spatially into 2x (128x64, full K) sub-tiles -> short
// 0.5T fourth wave. No atomics, bitwise-identical math.
// Round-13 fix: B fragment k-half selector is bHi=(lane>>3)&1 (round-12
// template refactor wrongly substituted aHi, scrambling B fragments).

#define N_DIM 4096
constexpr int KTILE = 64;
constexpr int NKT = N_DIM / KTILE;           // 64
constexpr int STAGE_BYTES = 2 * 128 * 128;   // A 16KB + B 16KB
constexpr int SMEM_BYTES = 3 * STAGE_BYTES;  // 98304
constexpr int FULL_CTAS = 888;               // 3 waves x 296 slots
constexpr int NTILES = 1024;
constexpr int TAIL_TILES = NTILES - FULL_CTAS;        // 136
constexpr int GRID = FULL_CTAS + 2 * TAIL_TILES;      // 1160

__device__ __half g_xh[(size_t)N_DIM * N_DIM];
__device__ __half g_wb[(size_t)N_DIM * N_DIM];

// ---------------------------------------------------------------------------
// prep: binarize W -> fp16, cast x -> fp16
// ---------------------------------------------------------------------------
__global__ void prep_kernel(const float4* __restrict__ x,
                            const float4* __restrict__ W, int n4) {
    int i = blockIdx.x * blockDim.x + threadIdx.x;
    if (i >= n4) return;
    float4 xv = x[i];
    float4 wv = W[i];
    float xs[4] = {xv.x, xv.y, xv.z, xv.w};
    float ws[4] = {wv.x, wv.y, wv.z, wv.w};
    alignas(8) __half xh[4], wb[4];
#pragma unroll
    for (int j = 0; j < 4; j++) {
        xh[j] = __float2half_rn(xs[j]);
        float s = (ws[j] > 0.0f) ? 1.0f : ((ws[j] < 0.0f) ? -1.0f : 0.0f);
        wb[j] = __float2half_rn(s);
    }
    size_t base = (size_t)i * 4;
    *reinterpret_cast<uint2*>(g_xh + base) = *reinterpret_cast<uint2*>(xh);
    *reinterpret_cast<uint2*>(g_wb + base) = *reinterpret_cast<uint2*>(wb);
}

// ---------------------------------------------------------------------------
// PTX helpers
// ---------------------------------------------------------------------------
__device__ __forceinline__ void cp16(uint32_t smem_addr, const void* gmem_ptr) {
    asm volatile("cp.async.cg.shared.global [%0], [%1], 16;\n"
                 :: "r"(smem_addr), "l"(gmem_ptr) : "memory");
}

__device__ __forceinline__ void ldsm_x4(uint32_t* r, uint32_t a) {
    asm volatile("ldmatrix.sync.aligned.m8n8.x4.shared.b16 {%0,%1,%2,%3}, [%4];\n"
                 : "=r"(r[0]), "=r"(r[1]), "=r"(r[2]), "=r"(r[3]) : "r"(a));
}

__device__ __forceinline__ void mma16816(float* d, const uint32_t* a,
                                         const uint32_t* b) {
    asm volatile("mma.sync.aligned.m16n8k16.row.col.f32.f16.f16.f32 "
                 "{%0,%1,%2,%3},{%4,%5,%6,%7},{%8,%9},{%0,%1,%2,%3};\n"
                 : "+f"(d[0]), "+f"(d[1]), "+f"(d[2]), "+f"(d[3])
                 : "r"(a[0]), "r"(a[1]), "r"(a[2]), "r"(a[3]),
                   "r"(b[0]), "r"(b[1]));
}

// ---------------------------------------------------------------------------
// One output tile: 128 x (NPR*32), full K. 4 warps: 2(M) x 2(N),
// warp tile 64 x (NPR*16). NPR=4 -> 128x128 tile, NPR=2 -> 128x64.
// Stage layout: A rows 0-127 (128B/row XOR-swizzled); B rows 0..NPR*32-1
// at +16384 same. Swizzle: off(row, ch16) = row*128 + ((ch16 ^ (row&7)) << 4)
// ---------------------------------------------------------------------------
template <int NPR>
__device__ __forceinline__ void tile_compute(
    int mBase, int nBase, uint32_t smem_base,
    const float* __restrict__ bias, float* __restrict__ out) {

    const int tid   = threadIdx.x;
    const int lane  = tid & 31;
    const int warp  = tid >> 5;
    const int warpM = warp & 1;
    const int warpN = warp >> 1;

    float acc[4][2 * NPR][4];
#pragma unroll
    for (int a = 0; a < 4; a++)
#pragma unroll
        for (int b = 0; b < 2 * NPR; b++)
#pragma unroll
            for (int c = 0; c < 4; c++) acc[a][b][c] = 0.0f;

    // ---- cp.async per-thread mapping: ch16 = tid&7, rows rbase + p*16 ----
    const int rbase = tid >> 3;               // 0..15
    const int ch    = tid & 7;
    const uint32_t swA = (uint32_t)rbase * 128 + (uint32_t)((ch ^ (rbase & 7)) << 4);
    const __half* gA = g_xh + (size_t)(mBase + rbase) * N_DIM + ch * 8;
    const __half* gB = g_wb + (size_t)(nBase + rbase) * N_DIM + ch * 8;

    auto prefetch = [&](int kt) {
        const uint32_t sb = smem_base + (uint32_t)(kt % 3) * STAGE_BYTES;
        const int k0 = kt * KTILE;
#pragma unroll
        for (int p = 0; p < 8; p++)
            cp16(sb + swA + (uint32_t)p * 2048, gA + (size_t)p * 16 * N_DIM + k0);
#pragma unroll
        for (int p = 0; p < 2 * NPR; p++)
            cp16(sb + 16384 + swA + (uint32_t)p * 2048,
                 gB + (size_t)p * 16 * N_DIM + k0);
        asm volatile("cp.async.commit_group;\n" ::: "memory");
    };

    // ---- ldmatrix per-thread row/offset precompute ----
    const uint32_t la7 = lane & 7;
    const uint32_t aHi = (lane >> 4) & 1;     // k +8 selector for A
    const uint32_t bHi = (lane >> 3) & 1;     // k +8 selector for B
    uint32_t aOff[4], bOff[NPR];
#pragma unroll
    for (int tm = 0; tm < 4; tm++) {
        uint32_t r = warpM * 64 + tm * 16 + (lane & 15);
        aOff[tm] = r * 128;
    }
#pragma unroll
    for (int pr = 0; pr < NPR; pr++) {
        uint32_t r = warpN * (16 * NPR) + pr * 16 + la7 + ((lane >> 4) & 1) * 8;
        bOff[pr] = 16384 + r * 128;
    }

    uint32_t ah[2][4][4], bq[2][NPR][4];

    auto loadfrags = [&](uint32_t sb, int ks, int buf) {
        const uint32_t ca = (((uint32_t)ks * 2 + aHi) ^ la7) << 4;
        const uint32_t cb = (((uint32_t)ks * 2 + bHi) ^ la7) << 4;
#pragma unroll
        for (int tm = 0; tm < 4; tm++) ldsm_x4(ah[buf][tm], sb + aOff[tm] + ca);
#pragma unroll
        for (int pr = 0; pr < NPR; pr++) ldsm_x4(bq[buf][pr], sb + bOff[pr] + cb);
    };

    auto mmas = [&](int buf) {
#pragma unroll
        for (int tm = 0; tm < 4; tm++)
#pragma unroll
            for (int pr = 0; pr < NPR; pr++) {
                mma16816(acc[tm][2 * pr],     ah[buf][tm], &bq[buf][pr][0]);
                mma16816(acc[tm][2 * pr + 1], ah[buf][tm], &bq[buf][pr][2]);
            }
    };

    prefetch(0);
    prefetch(1);
    asm volatile("cp.async.wait_group 1;\n" ::: "memory");
    __syncthreads();
    loadfrags(smem_base, 0, 0);   // (kt=0, ks=0) into buf 0

    for (int kt = 0; kt < NKT; kt++) {
        const uint32_t sb = smem_base + (uint32_t)(kt % 3) * STAGE_BYTES;
#pragma unroll
        for (int ks = 0; ks < 3; ks++) {
            loadfrags(sb, ks + 1, (ks + 1) & 1);
            mmas(ks & 1);
        }
        // ks3 frags in buf 1, not yet crunched
        if (kt + 2 < NKT) prefetch(kt + 2);
        if (kt + 1 < NKT) {
            if (kt + 2 < NKT)
                asm volatile("cp.async.wait_group 1;\n" ::: "memory");
            else
                asm volatile("cp.async.wait_group 0;\n" ::: "memory");
            __syncthreads();
            loadfrags(smem_base + (uint32_t)((kt + 1) % 3) * STAGE_BYTES, 0, 0);
        }
        mmas(1);   // keeps tensor pipe busy through the sync window
    }

    // ---- epilogue: + bias, fp32 store ----
    const int g  = lane >> 2;
    const int t4 = lane & 3;
#pragma unroll
    for (int tm = 0; tm < 4; tm++) {
        int rr = mBase + warpM * 64 + tm * 16 + g;
#pragma unroll
        for (int tn = 0; tn < 2 * NPR; tn++) {
            int col = nBase + warpN * (16 * NPR) + tn * 8 + 2 * t4;
            float2 b2 = *reinterpret_cast<const float2*>(bias + col);
            float2 v0, v1;
            v0.x = acc[tm][tn][0] + b2.x;
            v0.y = acc[tm][tn][1] + b2.y;
            v1.x = acc[tm][tn][2] + b2.x;
            v1.y = acc[tm][tn][3] + b2.y;
            *reinterpret_cast<float2*>(out + (size_t)rr * N_DIM + col)       = v0;
            *reinterpret_cast<float2*>(out + (size_t)(rr + 8) * N_DIM + col) = v1;
        }
    }
}

__global__ void __launch_bounds__(128, 2)
gemm_kernel(const float* __restrict__ bias, float* __restrict__ out) {
    extern __shared__ char smem[];
    const uint32_t smem_base = (uint32_t)__cvta_generic_to_shared(smem);
    const int bid = blockIdx.x;

    if (bid < FULL_CTAS) {
        // full 128x128 tile; linear tile id, row-major (A reuse within a wave)
        const int mT = bid >> 5, nT = bid & 31;
        tile_compute<4>(mT * 128, nT * 128, smem_base, bias, out);
    } else {
        // tail: tiles FULL_CTAS..1023 split into two 128x64 sub-tiles (full K)
        const int q  = bid - FULL_CTAS;
        const int t  = FULL_CTAS + (q >> 1);
        const int h  = q & 1;
        const int mT = t >> 5, nT = t & 31;
        tile_compute<2>(mT * 128, nT * 128 + h * 64, smem_base, bias, out);
    }
}

// ---------------------------------------------------------------------------
extern "C" void kernel_launch(void* const* d_in, const int* in_sizes, int n_in,
                              void* d_out, int out_size) {
    const float* x = (const float*)d_in[0];
    const float* W = (const float*)d_in[1];
    const float* b = (const float*)d_in[2];
    float* out = (float*)d_out;

    const int n4 = (N_DIM * N_DIM) / 4;
    prep_kernel<<<(n4 + 255) / 256, 256>>>((const float4*)x, (const float4*)W, n4);

    cudaFuncSetAttribute(gemm_kernel, cudaFuncAttributeMaxDynamicSharedMemorySize,
                         SMEM_BYTES);
    gemm_kernel<<<GRID, 128, SMEM_BYTES>>>(b, out);
}